// round 5
// baseline (speedup 1.0000x reference)
#include <cuda_runtime.h>

// Problem constants (fixed shapes per reference)
#define BB 8
#define TT 32768
#define FIN 64
#define HID 32
#define FF 64
#define NS 64
#define TB 256                   // timesteps per k1 block
#define SUBL 64                  // scan sub-chunk length
#define NSUB (BB * TT / SUBL)    // 4096 sub-chunks total
#define SUBPB (TT / SUBL)        // 512 sub-chunks per batch

// Derived parameters + scratch (device globals: no allocation allowed)
__device__ float g_A[NS];        // decay per state
__device__ float g_A64[NS];      // A^64
__device__ float g_w[NS];        // C*P per state
__device__ float g_wU[HID];      // W2 @ Wu
__device__ float g_wD[HID];      // W2 @ D
__device__ float g_cU;           // b2 @ Wu
__device__ float g_cDy;          // b2 @ D + b_y
__device__ float g_u[BB * TT];         // scalar drive per timestep
__device__ float g_end[NSUB * NS];     // per-sub-chunk local end states
__device__ float g_carry[NSUB * NS];   // carry-in state per sub-chunk

// ---------------- packed f32x2 helpers ----------------
__device__ __forceinline__ unsigned long long pack2(float lo, float hi) {
    unsigned long long r;
    asm("mov.b64 %0, {%1,%2};" : "=l"(r) : "f"(lo), "f"(hi));
    return r;
}
__device__ __forceinline__ void unpack2(unsigned long long v, float& lo, float& hi) {
    asm("mov.b64 {%0,%1}, %2;" : "=f"(lo), "=f"(hi) : "l"(v));
}
__device__ __forceinline__ void fma2(unsigned long long& d,
                                     unsigned long long a, unsigned long long b) {
    asm("fma.rn.f32x2 %0, %1, %2, %0;" : "+l"(d) : "l"(a), "l"(b));
}

// ---------------------------------------------------------------------------
// K0: derive folded parameters. One block, 64 threads.
// ---------------------------------------------------------------------------
__global__ void k0_params(const float* __restrict__ W2, const float* __restrict__ b2,
                          const float* __restrict__ Lraw, const float* __restrict__ P,
                          const float* __restrict__ Wu, const float* __restrict__ Cv,
                          const float* __restrict__ Dv, const float* __restrict__ b_y) {
    int tid = threadIdx.x;
    if (tid < NS) {
        float lr = Lraw[tid];
        float sp = (lr > 20.f) ? lr : log1pf(expf(lr));   // softplus
        g_A[tid]   = expf(-sp);
        g_A64[tid] = expf(-sp * (float)SUBL);
        g_w[tid]   = Cv[tid] * P[tid];
    }
    if (tid < HID) {
        float su = 0.f, sd = 0.f;
        for (int f = 0; f < FF; f++) {
            float w2 = W2[tid * FF + f];
            su = fmaf(w2, Wu[f], su);
            sd = fmaf(w2, Dv[f], sd);
        }
        g_wU[tid] = su;
        g_wD[tid] = sd;
    }
    if (tid == 0) {
        float cu = 0.f, cd = 0.f;
        for (int f = 0; f < FF; f++) {
            cu = fmaf(b2[f], Wu[f], cu);
            cd = fmaf(b2[f], Dv[f], cd);
        }
        g_cU  = cu;
        g_cDy = cd + b_y[0];
    }
}

// ---------------------------------------------------------------------------
// K1: MLP GEMM, packed f32x2 over COLUMN pairs, transposed x staging.
// Block = 256 timesteps, 128 threads. Thread (rg=tid>>2, cg=tid&3) computes
// rows rg*8..+7, cols cg*8..+7 as acc[8 rows][4 col-pairs].
// Weight pairs come directly from LDS.128 (zero movs). x is staged transposed
// with stride-261 rows and an XOR-4 row permutation per 32-row block
// (true permutation; conflict-free on both store and read paths).
// ---------------------------------------------------------------------------
__global__ void __launch_bounds__(128, 4) k1_mlp(const float* __restrict__ x,
                                                 const float* __restrict__ W1,
                                                 const float* __restrict__ b1,
                                                 float* __restrict__ yout) {
    __shared__ __align__(16) float xs[32][261];     // transposed k-half
    __shared__ __align__(16) float W1s[FIN * HID];  // 8 KB
    __shared__ __align__(16) float us[TB];
    __shared__ __align__(16) float ds[TB];

    const int tid = threadIdx.x;
    const int cg  = tid & 3;
    const int rg  = tid >> 2;            // 0..31
    const int base = rg * 8;             // first row of this thread
    const int c0  = cg * 8;              // first col of this thread
    const int chunk = blockIdx.x;
    const long t0 = (long)chunk * TB;

    // Stage full W1 (64x32)
    for (int e = tid; e < FIN * HID; e += 128) W1s[e] = W1[e];

    // accumulators: 8 rows x 4 col-pairs, init to bias pairs
    unsigned long long acc[8][4];
    #pragma unroll
    for (int p = 0; p < 4; p++) {
        unsigned long long bp = pack2(b1[c0 + 2 * p], b1[c0 + 2 * p + 1]);
        #pragma unroll
        for (int r = 0; r < 8; r++) acc[r][p] = bp;
    }

    const float4* xg = (const float4*)(x + t0 * FIN);
    // XOR swizzle amount for this thread's 32-row block
    const int xsw = 4 * ((rg >> 2) & 1);

    #pragma unroll
    for (int s = 0; s < 2; s++) {
        __syncthreads();   // protect xs from previous stage's readers
        // stage x[:, s*32 .. s*32+31] transposed: xs[k][row ^ xor-swizzle]
        #pragma unroll
        for (int i = 0; i < 16; i++) {
            int e = tid + i * 128;          // 0..2047
            int row = e >> 3;
            int q   = e & 7;
            float4 v = xg[row * 16 + s * 8 + q];
            int pr = row ^ (4 * ((row >> 5) & 1));   // permutation
            xs[4 * q + 0][pr] = v.x;
            xs[4 * q + 1][pr] = v.y;
            xs[4 * q + 2][pr] = v.z;
            xs[4 * q + 3][pr] = v.w;
        }
        __syncthreads();

        #pragma unroll 4
        for (int kl = 0; kl < 32; kl++) {
            // weight pairs: 2x LDS.128 -> 4 natural u64 pairs
            const ulonglong2* wrow =
                (const ulonglong2*)&W1s[(s * 32 + kl) * HID + c0];
            ulonglong2 wA = wrow[0];
            ulonglong2 wB = wrow[1];
            // x for logical rows base..base+7: physical index base + (r^xsw)
            const float* xrow = &xs[kl][base];
            unsigned long long xd[8];
            #pragma unroll
            for (int r = 0; r < 8; r++) {
                float xv = xrow[r ^ xsw];
                xd[r] = pack2(xv, xv);
            }
            #pragma unroll
            for (int r = 0; r < 8; r++) {
                fma2(acc[r][0], xd[r], wA.x);
                fma2(acc[r][1], xd[r], wA.y);
                fma2(acc[r][2], xd[r], wB.x);
                fma2(acc[r][3], xd[r], wB.y);
            }
        }
    }

    // Epilogue: relu + project to (u, d) over this thread's 8 cols
    float uu[8], dd[8];
    #pragma unroll
    for (int r = 0; r < 8; r++) { uu[r] = 0.f; dd[r] = 0.f; }
    #pragma unroll
    for (int p = 0; p < 4; p++) {
        float wu0 = g_wU[c0 + 2 * p], wu1 = g_wU[c0 + 2 * p + 1];
        float wd0 = g_wD[c0 + 2 * p], wd1 = g_wD[c0 + 2 * p + 1];
        #pragma unroll
        for (int r = 0; r < 8; r++) {
            float h0, h1;
            unpack2(acc[r][p], h0, h1);
            h0 = fmaxf(h0, 0.f); h1 = fmaxf(h1, 0.f);
            uu[r] = fmaf(h0, wu0, fmaf(h1, wu1, uu[r]));
            dd[r] = fmaf(h0, wd0, fmaf(h1, wd1, dd[r]));
        }
    }
    // reduce across the 4 column-groups (xor lanes 1,2)
    #pragma unroll
    for (int r = 0; r < 8; r++) {
        uu[r] += __shfl_xor_sync(0xffffffffu, uu[r], 1);
        uu[r] += __shfl_xor_sync(0xffffffffu, uu[r], 2);
        dd[r] += __shfl_xor_sync(0xffffffffu, dd[r], 1);
        dd[r] += __shfl_xor_sync(0xffffffffu, dd[r], 2);
    }
    if (cg == 0) {
        float cU = g_cU, cDy = g_cDy;
        #pragma unroll
        for (int r = 0; r < 8; r++) {
            us[base + r] = uu[r] + cU;
            ds[base + r] = dd[r] + cDy;
        }
    }
    __syncthreads();

    // cooperative stores of u and the feedthrough part of y
    if (tid < 64) {
        ((float4*)(g_u + t0))[tid]  = ((const float4*)us)[tid];
        ((float4*)(yout + t0))[tid] = ((const float4*)ds)[tid];
    }

    // local end-states of the 4 sub-chunks (64 steps each), zero init.
    // warp w handles sub-chunk w; lane holds states (lane, lane+32).
    {
        const int w = tid >> 5;
        const int lane = tid & 31;
        float a0 = g_A[lane], a1 = g_A[lane + 32];
        float r0 = 0.f, r1 = 0.f;
        const float* up = &us[w * SUBL];
        #pragma unroll 8
        for (int t = 0; t < SUBL; t++) {
            float uv = up[t];
            r0 = fmaf(a0, r0, uv);
            r1 = fmaf(a1, r1, uv);
        }
        const int sub = chunk * 4 + w;
        g_end[sub * NS + lane]      = r0;
        g_end[sub * NS + lane + 32] = r1;
    }
}

// ---------------------------------------------------------------------------
// K2: scan carries across sub-chunks, per batch. One block per batch,
// 64 threads (thread = state). 32-wide prefetch to cover load latency.
// ---------------------------------------------------------------------------
__global__ void __launch_bounds__(NS) k2_carry() {
    const int b = blockIdx.x;
    const int n = threadIdx.x;
    const float al = g_A64[n];
    float carry = 0.f;
    const float* ep = &g_end[(long)b * SUBPB * NS + n];
    float* cp = &g_carry[(long)b * SUBPB * NS + n];
    for (int c = 0; c < SUBPB; c += 32) {
        float e[32];
        #pragma unroll
        for (int k = 0; k < 32; k++) e[k] = ep[(c + k) * NS];
        #pragma unroll
        for (int k = 0; k < 32; k++) {
            cp[(c + k) * NS] = carry;
            carry = fmaf(al, carry, e[k]);
        }
    }
}

// ---------------------------------------------------------------------------
// K3: replay each 64-step sub-chunk with its carry; deferred reduction.
// 8 warps per block, one warp per sub-chunk.
// ---------------------------------------------------------------------------
__global__ void __launch_bounds__(256) k3_scan(float* __restrict__ yout) {
    __shared__ __align__(16) float uss[8][SUBL];
    __shared__ float ps[8][32][33];
    const int lane = threadIdx.x & 31;
    const int w    = threadIdx.x >> 5;
    const int sub  = blockIdx.x * 8 + w;
    const long t0  = (long)sub * SUBL;

    if (lane < 16)
        ((float4*)uss[w])[lane] = ((const float4*)(g_u + t0))[lane];

    float a0 = g_A[lane],  a1 = g_A[lane + 32];
    float w0 = g_w[lane],  w1 = g_w[lane + 32];
    float r0 = g_carry[sub * NS + lane];
    float r1 = g_carry[sub * NS + lane + 32];
    __syncwarp();

    #pragma unroll
    for (int tb = 0; tb < SUBL / 32; tb++) {
        const float* up = &uss[w][tb * 32];
        #pragma unroll
        for (int j = 0; j < 32; j++) {
            float uv = up[j];
            r0 = fmaf(a0, r0, uv);
            r1 = fmaf(a1, r1, uv);
            ps[w][j][lane] = fmaf(w1, r1, w0 * r0);
        }
        __syncwarp();
        // lane reduces timestep 'lane' of this tile; 4 partial chains
        float s0 = 0.f, s1 = 0.f, s2 = 0.f, s3 = 0.f;
        const float* pr = ps[w][lane];
        #pragma unroll
        for (int j2 = 0; j2 < 32; j2 += 4) {
            s0 += pr[j2]; s1 += pr[j2 + 1]; s2 += pr[j2 + 2]; s3 += pr[j2 + 3];
        }
        yout[t0 + tb * 32 + lane] += (s0 + s1) + (s2 + s3);
        __syncwarp();
    }
}

// ---------------------------------------------------------------------------
extern "C" void kernel_launch(void* const* d_in, const int* in_sizes, int n_in,
                              void* d_out, int out_size) {
    const float* x    = (const float*)d_in[0];
    const float* W1   = (const float*)d_in[1];
    const float* b1   = (const float*)d_in[2];
    const float* W2   = (const float*)d_in[3];
    const float* b2   = (const float*)d_in[4];
    const float* Lraw = (const float*)d_in[5];
    const float* P    = (const float*)d_in[6];
    const float* Wu   = (const float*)d_in[7];
    const float* Cv   = (const float*)d_in[8];
    const float* Dv   = (const float*)d_in[9];
    const float* b_y  = (const float*)d_in[10];
    float* y = (float*)d_out;

    k0_params<<<1, 64>>>(W2, b2, Lraw, P, Wu, Cv, Dv, b_y);
    k1_mlp<<<BB * TT / TB, 128>>>(x, W1, b1, y);
    k2_carry<<<BB, NS>>>();
    k3_scan<<<NSUB / 8, 256>>>(y);
}